// round 9
// baseline (speedup 1.0000x reference)
#include <cuda_runtime.h>

// CCM_77043123355820: per-frequency 3x3 complex tap filter + cache shift.
// F_BINS = 257.
// Inputs (metadata order): m (27*257 f32), x (257*2 f32), cache (257*2*2 f32)
// Output: x_enh (257*2 f32) followed by new_cache (257*2*2 f32) = 1542 f32.
// NOTE: new_cache region starts at float offset 514 (byte 2056) -> only 8B
// aligned, so stores there must be float2, not float4.
//
// R9 = resubmit of R8 (round 8 died to a GB300 container infra failure, not a
// kernel error). R8 merges the best-measured properties: 3x96 launch shape
// (fewest CTAs to dispatch; hit the 4.576us floor in R7) + unthrottled
// register budget via __launch_bounds__(96, 1) (R7's implicit occupancy
// target capped regs at 32 and serialized the 27 m-loads on the cold path,
// cold ncu 4.13 -> 5.63us).

#define F_BINS 257

__global__ void __launch_bounds__(96, 1) ccm_kernel(
    const float* __restrict__ m,
    const float* __restrict__ x,
    const float* __restrict__ cache,
    float* __restrict__ out)
{
    int f = blockIdx.x * blockDim.x + threadIdx.x;
    if (f >= F_BINS) return;

    const float4* __restrict__ c4 = (const float4*)cache;  // (c0r,c0i,c1r,c1i) per f
    const float2* __restrict__ x2 = (const float2*)x;      // (xr,xi) per f

    // ---- gather X window at f-1, f, f+1 (vector loads, branchless zero mask) ----
    int gm = f - 1;
    int gp = f + 1;
    float wl = (gm >= 0)     ? 1.0f : 0.0f;
    float wr = (gp < F_BINS) ? 1.0f : 0.0f;
    int gml = (gm >= 0)     ? gm : 0;
    int gpc = (gp < F_BINS) ? gp : F_BINS - 1;

    float4 cl = c4[gml];
    float4 cc = c4[f];
    float4 cr = c4[gpc];
    float2 xl  = x2[gml];
    float2 xc  = x2[f];
    float2 xr2 = x2[gpc];

    // Xr[i][j], Xi[i][j]: i=time (0,1 from cache; 2 from x), j=freq offset
    float Xr[3][3], Xi[3][3];
    Xr[0][0] = cl.x * wl;  Xi[0][0] = cl.y * wl;
    Xr[1][0] = cl.z * wl;  Xi[1][0] = cl.w * wl;
    Xr[2][0] = xl.x * wl;  Xi[2][0] = xl.y * wl;
    Xr[0][1] = cc.x;       Xi[0][1] = cc.y;
    Xr[1][1] = cc.z;       Xi[1][1] = cc.w;
    Xr[2][1] = xc.x;       Xi[2][1] = xc.y;
    Xr[0][2] = cr.x * wr;  Xi[0][2] = cr.y * wr;
    Xr[1][2] = cr.z * wr;  Xi[1][2] = cr.w * wr;
    Xr[2][2] = xr2.x * wr; Xi[2][2] = xr2.y * wr;

    // ---- new_cache: shift time window (two 8B-aligned float2 stores) ----
    float2* nc2 = (float2*)(out + 2 * F_BINS);
    nc2[f * 2 + 0] = make_float2(cc.z, cc.w);
    nc2[f * 2 + 1] = xc;

    // ---- accumulate complex taps ----
    const float S3H = 0.86602540378443864676f;  // sqrt(3)/2
    float acc_r = 0.0f, acc_i = 0.0f;
#pragma unroll
    for (int i = 0; i < 3; i++) {
#pragma unroll
        for (int j = 0; j < 3; j++) {
            int k = i * 3 + j;
            float m0 = __ldg(&m[(0 * 9 + k) * F_BINS + f]);
            float m1 = __ldg(&m[(1 * 9 + k) * F_BINS + f]);
            float m2 = __ldg(&m[(2 * 9 + k) * F_BINS + f]);
            float Mr = fmaf(-0.5f, m1 + m2, m0);
            float Mi = S3H * (m1 - m2);
            float vr = Xr[i][j], vi = Xi[i][j];
            acc_r = fmaf(Mr, vr, acc_r);
            acc_r = fmaf(-Mi, vi, acc_r);
            acc_i = fmaf(Mr, vi, acc_i);
            acc_i = fmaf(Mi, vr, acc_i);
        }
    }

    ((float2*)out)[f] = make_float2(acc_r, acc_i);
}

extern "C" void kernel_launch(void* const* d_in, const int* in_sizes, int n_in,
                              void* d_out, int out_size) {
    const float* m     = (const float*)d_in[0];
    const float* x     = (const float*)d_in[1];
    const float* cache = (const float*)d_in[2];
    float* out = (float*)d_out;

    ccm_kernel<<<(F_BINS + 95) / 96, 96>>>(m, x, cache, out);
}

// round 10
// speedup vs baseline: 1.0482x; 1.0482x over previous
#include <cuda_runtime.h>

// CCM_77043123355820: per-frequency 3x3 complex tap filter + cache shift.
// F_BINS = 257.
// Inputs (metadata order): m (27*257 f32), x (257*2 f32), cache (257*2*2 f32)
// Output: x_enh (257*2 f32) followed by new_cache (257*2*2 f32) = 1542 f32.
// NOTE: new_cache region starts at float offset 514 (byte 2056) -> only 8B
// aligned, so stores there must be float2, not float4.
//
// R10 = R9 body, launch shape 1 CTA x 288 threads (9 warps on one SM).
// Final point on the launch-shape axis (9/3/1 CTAs). Kernel is at the
// single-launch latency floor: identical-source wallclock spans
// 4.576..6.91us; cold ncu ~4.1-4.5us dominated by T_ovh (~5000 cyc launch
// overhead) + one L2 latency round. All pipes <1%.

#define F_BINS 257

__global__ void __launch_bounds__(288, 1) ccm_kernel(
    const float* __restrict__ m,
    const float* __restrict__ x,
    const float* __restrict__ cache,
    float* __restrict__ out)
{
    int f = threadIdx.x;
    if (f >= F_BINS) return;

    const float4* __restrict__ c4 = (const float4*)cache;  // (c0r,c0i,c1r,c1i) per f
    const float2* __restrict__ x2 = (const float2*)x;      // (xr,xi) per f

    // ---- gather X window at f-1, f, f+1 (vector loads, branchless zero mask) ----
    int gm = f - 1;
    int gp = f + 1;
    float wl = (gm >= 0)     ? 1.0f : 0.0f;
    float wr = (gp < F_BINS) ? 1.0f : 0.0f;
    int gml = (gm >= 0)     ? gm : 0;
    int gpc = (gp < F_BINS) ? gp : F_BINS - 1;

    float4 cl = c4[gml];
    float4 cc = c4[f];
    float4 cr = c4[gpc];
    float2 xl  = x2[gml];
    float2 xc  = x2[f];
    float2 xr2 = x2[gpc];

    // Xr[i][j], Xi[i][j]: i=time (0,1 from cache; 2 from x), j=freq offset
    float Xr[3][3], Xi[3][3];
    Xr[0][0] = cl.x * wl;  Xi[0][0] = cl.y * wl;
    Xr[1][0] = cl.z * wl;  Xi[1][0] = cl.w * wl;
    Xr[2][0] = xl.x * wl;  Xi[2][0] = xl.y * wl;
    Xr[0][1] = cc.x;       Xi[0][1] = cc.y;
    Xr[1][1] = cc.z;       Xi[1][1] = cc.w;
    Xr[2][1] = xc.x;       Xi[2][1] = xc.y;
    Xr[0][2] = cr.x * wr;  Xi[0][2] = cr.y * wr;
    Xr[1][2] = cr.z * wr;  Xi[1][2] = cr.w * wr;
    Xr[2][2] = xr2.x * wr; Xi[2][2] = xr2.y * wr;

    // ---- new_cache: shift time window (two 8B-aligned float2 stores) ----
    float2* nc2 = (float2*)(out + 2 * F_BINS);
    nc2[f * 2 + 0] = make_float2(cc.z, cc.w);
    nc2[f * 2 + 1] = xc;

    // ---- accumulate complex taps ----
    const float S3H = 0.86602540378443864676f;  // sqrt(3)/2
    float acc_r = 0.0f, acc_i = 0.0f;
#pragma unroll
    for (int i = 0; i < 3; i++) {
#pragma unroll
        for (int j = 0; j < 3; j++) {
            int k = i * 3 + j;
            float m0 = __ldg(&m[(0 * 9 + k) * F_BINS + f]);
            float m1 = __ldg(&m[(1 * 9 + k) * F_BINS + f]);
            float m2 = __ldg(&m[(2 * 9 + k) * F_BINS + f]);
            float Mr = fmaf(-0.5f, m1 + m2, m0);
            float Mi = S3H * (m1 - m2);
            float vr = Xr[i][j], vi = Xi[i][j];
            acc_r = fmaf(Mr, vr, acc_r);
            acc_r = fmaf(-Mi, vi, acc_r);
            acc_i = fmaf(Mr, vi, acc_i);
            acc_i = fmaf(Mi, vr, acc_i);
        }
    }

    ((float2*)out)[f] = make_float2(acc_r, acc_i);
}

extern "C" void kernel_launch(void* const* d_in, const int* in_sizes, int n_in,
                              void* d_out, int out_size) {
    const float* m     = (const float*)d_in[0];
    const float* x     = (const float*)d_in[1];
    const float* cache = (const float*)d_in[2];
    float* out = (float*)d_out;

    ccm_kernel<<<1, 288>>>(m, x, cache, out);
}

// round 11
// speedup vs baseline: 1.2083x; 1.1528x over previous
#include <cuda_runtime.h>

// CCM_77043123355820: per-frequency 3x3 complex tap filter + cache shift.
// F_BINS = 257.
// Inputs (metadata order): m (27*257 f32), x (257*2 f32), cache (257*2*2 f32)
// Output: x_enh (257*2 f32) followed by new_cache (257*2*2 f32) = 1542 f32.
// NOTE: new_cache region starts at float offset 514 (byte 2056) -> only 8B
// aligned, so stores there must be float2, not float4.
//
// R11 = exact R4 source (most floor-hits: 4.576us). CONVERGED.
// Evidence: launch-shape axis fully mapped (9/3/1 CTAs -> same wallclock
// distribution 4.58..6.91us); cold ncu 4.0-4.5us = T_ovh + one L2 round;
// all pipes <1%; traffic is provably minimal (every input byte read once,
// every output byte written once, single launch). Remaining variance is
// harness replay-timing noise, not kernel behavior.

#define F_BINS 257

__global__ void __launch_bounds__(32) ccm_kernel(
    const float* __restrict__ m,
    const float* __restrict__ x,
    const float* __restrict__ cache,
    float* __restrict__ out)
{
    int f = blockIdx.x * blockDim.x + threadIdx.x;
    if (f >= F_BINS) return;

    const float4* __restrict__ c4 = (const float4*)cache;  // (c0r,c0i,c1r,c1i) per f
    const float2* __restrict__ x2 = (const float2*)x;      // (xr,xi) per f

    // ---- gather X window at f-1, f, f+1 (vector loads, branchless zero mask) ----
    int gm = f - 1;
    int gp = f + 1;
    float wl = (gm >= 0)     ? 1.0f : 0.0f;
    float wr = (gp < F_BINS) ? 1.0f : 0.0f;
    int gml = (gm >= 0)     ? gm : 0;
    int gpc = (gp < F_BINS) ? gp : F_BINS - 1;

    float4 cl = c4[gml];
    float4 cc = c4[f];
    float4 cr = c4[gpc];
    float2 xl  = x2[gml];
    float2 xc  = x2[f];
    float2 xr2 = x2[gpc];

    // Xr[i][j], Xi[i][j]: i=time (0,1 from cache; 2 from x), j=freq offset
    float Xr[3][3], Xi[3][3];
    Xr[0][0] = cl.x * wl;  Xi[0][0] = cl.y * wl;
    Xr[1][0] = cl.z * wl;  Xi[1][0] = cl.w * wl;
    Xr[2][0] = xl.x * wl;  Xi[2][0] = xl.y * wl;
    Xr[0][1] = cc.x;       Xi[0][1] = cc.y;
    Xr[1][1] = cc.z;       Xi[1][1] = cc.w;
    Xr[2][1] = xc.x;       Xi[2][1] = xc.y;
    Xr[0][2] = cr.x * wr;  Xi[0][2] = cr.y * wr;
    Xr[1][2] = cr.z * wr;  Xi[1][2] = cr.w * wr;
    Xr[2][2] = xr2.x * wr; Xi[2][2] = xr2.y * wr;

    // ---- new_cache: shift time window (two 8B-aligned float2 stores) ----
    float2* nc2 = (float2*)(out + 2 * F_BINS);
    nc2[f * 2 + 0] = make_float2(cc.z, cc.w);
    nc2[f * 2 + 1] = xc;

    // ---- accumulate complex taps ----
    const float S3H = 0.86602540378443864676f;  // sqrt(3)/2
    float acc_r = 0.0f, acc_i = 0.0f;
#pragma unroll
    for (int i = 0; i < 3; i++) {
#pragma unroll
        for (int j = 0; j < 3; j++) {
            int k = i * 3 + j;
            float m0 = __ldg(&m[(0 * 9 + k) * F_BINS + f]);
            float m1 = __ldg(&m[(1 * 9 + k) * F_BINS + f]);
            float m2 = __ldg(&m[(2 * 9 + k) * F_BINS + f]);
            float Mr = fmaf(-0.5f, m1 + m2, m0);
            float Mi = S3H * (m1 - m2);
            float vr = Xr[i][j], vi = Xi[i][j];
            acc_r = fmaf(Mr, vr, acc_r);
            acc_r = fmaf(-Mi, vi, acc_r);
            acc_i = fmaf(Mr, vi, acc_i);
            acc_i = fmaf(Mi, vr, acc_i);
        }
    }

    ((float2*)out)[f] = make_float2(acc_r, acc_i);
}

extern "C" void kernel_launch(void* const* d_in, const int* in_sizes, int n_in,
                              void* d_out, int out_size) {
    const float* m     = (const float*)d_in[0];
    const float* x     = (const float*)d_in[1];
    const float* cache = (const float*)d_in[2];
    float* out = (float*)d_out;

    ccm_kernel<<<(F_BINS + 31) / 32, 32>>>(m, x, cache, out);
}